// round 1
// baseline (speedup 1.0000x reference)
#include <cuda_runtime.h>
#include <math.h>

#define BB 2
#define NN 2048
#define DIM 1024
#define HH 16
#define DH 64
#define NNUL 2
#define JJ (NN + NNUL)
#define SCALE 8.0f
#define LN_EPS 1e-5f

// ---------------- scratch (static device globals: allocation-guard safe) ----
__device__ float g_xn[(size_t)BB * NN * DIM];          // LayerNorm'd x (Q path)
__device__ float g_qraw[(size_t)BB * NN * DIM];        // xn @ Wq
__device__ float g_kvraw[(size_t)BB * NN * 2 * DIM];   // x @ Wkv
__device__ float g_q[(size_t)BB * HH * NN * DH];       // normalized q, (b,h,n,d)
__device__ float g_k[(size_t)BB * HH * JJ * DH];       // normalized k incl nulls, (b,h,j,d)
__device__ float g_v[(size_t)BB * HH * JJ * DH];       // v incl nulls, (b,h,j,d)
__device__ float g_ao[(size_t)BB * NN * DIM];          // attention out, (b,n,h*dh)

// ---------------- LayerNorm ------------------------------------------------
__global__ void ln_kernel(const float* __restrict__ x, const float* __restrict__ gma,
                          const float* __restrict__ bta) {
    int row = blockIdx.x;
    const float* xr = x + (size_t)row * DIM;
    float vals[4];
    float s = 0.f, ss = 0.f;
#pragma unroll
    for (int i = 0; i < 4; i++) {
        float v = xr[threadIdx.x + i * 256];
        vals[i] = v;
        s += v;
        ss += v * v;
    }
#pragma unroll
    for (int off = 16; off; off >>= 1) {
        s += __shfl_xor_sync(0xffffffffu, s, off);
        ss += __shfl_xor_sync(0xffffffffu, ss, off);
    }
    __shared__ float rs[8], rss[8];
    int w = threadIdx.x >> 5;
    if ((threadIdx.x & 31) == 0) { rs[w] = s; rss[w] = ss; }
    __syncthreads();
    if (threadIdx.x < 32) {
        float a = (threadIdx.x < 8) ? rs[threadIdx.x] : 0.f;
        float b2 = (threadIdx.x < 8) ? rss[threadIdx.x] : 0.f;
#pragma unroll
        for (int off = 4; off; off >>= 1) {
            a += __shfl_xor_sync(0xffffffffu, a, off);
            b2 += __shfl_xor_sync(0xffffffffu, b2, off);
        }
        if (threadIdx.x == 0) { rs[0] = a; rss[0] = b2; }
    }
    __syncthreads();
    float mu = rs[0] * (1.0f / DIM);
    float var = rss[0] * (1.0f / DIM) - mu * mu;
    float inv = rsqrtf(var + LN_EPS);
#pragma unroll
    for (int i = 0; i < 4; i++) {
        int d = threadIdx.x + i * 256;
        g_xn[(size_t)row * DIM + d] = (vals[i] - mu) * inv * gma[d] + bta[d];
    }
}

// ---------------- fp32 SIMT GEMM: C = A(MxK) @ B(KxN), row-major -----------
#define GBM 128
#define GBN 128
#define GBK 16
#define GTM 8
#define GTN 8
__global__ void __launch_bounds__(256, 2)
sgemm_kernel(const float* __restrict__ A, const float* __restrict__ B,
             float* __restrict__ C, int M, int N, int K) {
    __shared__ float As[GBK][GBM];
    __shared__ float Bs[GBK][GBN];
    int tid = threadIdx.x;
    int tx = tid & 15;       // along N
    int ty = tid >> 4;       // along M
    int row0 = blockIdx.y * GBM;
    int col0 = blockIdx.x * GBN;
    float acc[GTM][GTN];
#pragma unroll
    for (int i = 0; i < GTM; i++)
#pragma unroll
        for (int j = 0; j < GTN; j++) acc[i][j] = 0.f;

    for (int k0 = 0; k0 < K; k0 += GBK) {
        // A tile: 128x16 -> As[k][m] (transpose). 512 float4 total, 2 per thread.
#pragma unroll
        for (int t = 0; t < 2; t++) {
            int i = tid + t * 256;
            int r = i >> 2;            // row in tile
            int c4 = i & 3;            // which float4 in k
            float4 a = *(const float4*)&A[(size_t)(row0 + r) * K + k0 + c4 * 4];
            As[c4 * 4 + 0][r] = a.x;
            As[c4 * 4 + 1][r] = a.y;
            As[c4 * 4 + 2][r] = a.z;
            As[c4 * 4 + 3][r] = a.w;
        }
        // B tile: 16x128 -> Bs[k][n]. 512 float4, 2 per thread.
#pragma unroll
        for (int t = 0; t < 2; t++) {
            int i = tid + t * 256;
            int r = i >> 5;            // k row (128/4 = 32 float4 per row)
            int c4 = i & 31;
            *(float4*)&Bs[r][c4 * 4] = *(const float4*)&B[(size_t)(k0 + r) * N + col0 + c4 * 4];
        }
        __syncthreads();
#pragma unroll
        for (int kk = 0; kk < GBK; kk++) {
            float ra[GTM], rb[GTN];
            *(float4*)&ra[0] = *(const float4*)&As[kk][ty * GTM];
            *(float4*)&ra[4] = *(const float4*)&As[kk][ty * GTM + 4];
            *(float4*)&rb[0] = *(const float4*)&Bs[kk][tx * GTN];
            *(float4*)&rb[4] = *(const float4*)&Bs[kk][tx * GTN + 4];
#pragma unroll
            for (int i = 0; i < GTM; i++)
#pragma unroll
                for (int j = 0; j < GTN; j++)
                    acc[i][j] = fmaf(ra[i], rb[j], acc[i][j]);
        }
        __syncthreads();
    }
#pragma unroll
    for (int i = 0; i < GTM; i++) {
#pragma unroll
        for (int j = 0; j < GTN; j += 4) {
            float4 v = make_float4(acc[i][j], acc[i][j + 1], acc[i][j + 2], acc[i][j + 3]);
            *(float4*)&C[(size_t)(row0 + ty * GTM + i) * N + col0 + tx * GTN + j] = v;
        }
    }
}

// ---------------- q prep: l2norm * q_scale, transpose to (b,h,n,d) ----------
__global__ void qprep_kernel(const float* __restrict__ qs) {
    int gw = blockIdx.x * 4 + (threadIdx.x >> 5);
    int lane = threadIdx.x & 31;
    int h = gw % HH;
    int n = (gw / HH) % NN;
    int b = gw / (HH * NN);
    const float* src = g_qraw + (size_t)(b * NN + n) * DIM + h * DH;
    float v0 = src[lane], v1 = src[lane + 32];
    float ss = v0 * v0 + v1 * v1;
#pragma unroll
    for (int off = 16; off; off >>= 1) ss += __shfl_xor_sync(0xffffffffu, ss, off);
    float inv = 1.0f / fmaxf(sqrtf(ss), 1e-12f);
    float* dst = g_q + (size_t)((b * HH + h) * NN + n) * DH;
    dst[lane] = v0 * inv * qs[lane];
    dst[lane + 32] = v1 * inv * qs[lane + 32];
}

// ---------------- kv prep: k l2norm * k_scale, v copy; (b,h,j,d) ------------
__global__ void kvprep_kernel(const float* __restrict__ ks) {
    int gw = blockIdx.x * 4 + (threadIdx.x >> 5);
    int lane = threadIdx.x & 31;
    int h = gw % HH;
    int n = (gw / HH) % NN;
    int b = gw / (HH * NN);
    const float* row = g_kvraw + (size_t)(b * NN + n) * (2 * DIM);
    float k0 = row[h * DH + lane], k1 = row[h * DH + lane + 32];
    float v0 = row[DIM + h * DH + lane], v1 = row[DIM + h * DH + lane + 32];
    float ss = k0 * k0 + k1 * k1;
#pragma unroll
    for (int off = 16; off; off >>= 1) ss += __shfl_xor_sync(0xffffffffu, ss, off);
    float inv = 1.0f / fmaxf(sqrtf(ss), 1e-12f);
    size_t base = (size_t)((b * HH + h) * JJ + (n + NNUL)) * DH;
    g_k[base + lane] = k0 * inv * ks[lane];
    g_k[base + lane + 32] = k1 * inv * ks[lane + 32];
    g_v[base + lane] = v0;
    g_v[base + lane + 32] = v1;
}

// ---------------- null kv prep ----------------------------------------------
__global__ void nullprep_kernel(const float* __restrict__ null_kv,
                                const float* __restrict__ ks) {
    int w = threadIdx.x >> 5;   // 0..31: (h, t)
    int lane = threadIdx.x & 31;
    int h = w / NNUL;
    int t = w % NNUL;
    const float* base = null_kv + (size_t)h * (2 * NNUL) * DH;
    float k0 = base[(2 * t) * DH + lane];
    float k1 = base[(2 * t) * DH + lane + 32];
    float vv0 = base[(2 * t + 1) * DH + lane];
    float vv1 = base[(2 * t + 1) * DH + lane + 32];
    float ss = k0 * k0 + k1 * k1;
#pragma unroll
    for (int off = 16; off; off >>= 1) ss += __shfl_xor_sync(0xffffffffu, ss, off);
    float inv = 1.0f / fmaxf(sqrtf(ss), 1e-12f);
    for (int b = 0; b < BB; b++) {
        size_t o = (size_t)((b * HH + h) * JJ + t) * DH;
        g_k[o + lane] = k0 * inv * ks[lane];
        g_k[o + lane + 32] = k1 * inv * ks[lane + 32];
        g_v[o + lane] = vv0;
        g_v[o + lane + 32] = vv1;
    }
}

// ---------------- attention (flash-style, 1 thread = 1 query row) -----------
#define TQ 64
#define TK 64
__global__ void __launch_bounds__(64)
attn_kernel() {
    __shared__ float4 Ks[TK * 16];
    __shared__ float4 Vs[TK * 16];
    int b = blockIdx.z, h = blockIdx.y, qt = blockIdx.x;
    int tid = threadIdx.x;
    int i = qt * TQ + tid;                 // query row
    const float* qrow = g_q + (size_t)((b * HH + h) * NN + i) * DH;
    float q[DH];
#pragma unroll
    for (int d = 0; d < DH; d += 4) {
        float4 t = *(const float4*)&qrow[d];
        q[d] = t.x; q[d + 1] = t.y; q[d + 2] = t.z; q[d + 3] = t.w;
    }
    float m = -1e30f, l = 0.f;
    float o[DH];
#pragma unroll
    for (int d = 0; d < DH; d++) o[d] = 0.f;

    float slope = exp2f(-0.5f * (float)(h + 1));
    int mycol = i + NNUL;                  // my max visible column (== ALiBi row pos)
    int nkeys = qt * TQ + TQ - 1 + NNUL + 1;  // block-max visible cols [0, nkeys)

    const float4* kbase = (const float4*)(g_k + (size_t)(b * HH + h) * JJ * DH);
    const float4* vbase = (const float4*)(g_v + (size_t)(b * HH + h) * JJ * DH);

    for (int j0 = 0; j0 < nkeys; j0 += TK) {
        int cnt = min(TK, nkeys - j0);
        for (int t = tid; t < cnt * 16; t += 64) {
            Ks[t] = kbase[(size_t)j0 * 16 + t];
            Vs[t] = vbase[(size_t)j0 * 16 + t];
        }
        __syncthreads();
        for (int jj = 0; jj < cnt; jj++) {
            int col = j0 + jj;
            if (col <= mycol) {
                float s = 0.f;
#pragma unroll
                for (int c = 0; c < 16; c++) {
                    float4 kk = Ks[jj * 16 + c];
                    s = fmaf(q[4 * c + 0], kk.x, s);
                    s = fmaf(q[4 * c + 1], kk.y, s);
                    s = fmaf(q[4 * c + 2], kk.z, s);
                    s = fmaf(q[4 * c + 3], kk.w, s);
                }
                s = s * SCALE + slope * (float)(col - mycol);  // col<=mycol -> bias<=0
                float mn = fmaxf(m, s);
                float corr = __expf(m - mn);
                float p = __expf(s - mn);
                l = l * corr + p;
#pragma unroll
                for (int c = 0; c < 16; c++) {
                    float4 vv = Vs[jj * 16 + c];
                    o[4 * c + 0] = o[4 * c + 0] * corr + p * vv.x;
                    o[4 * c + 1] = o[4 * c + 1] * corr + p * vv.y;
                    o[4 * c + 2] = o[4 * c + 2] * corr + p * vv.z;
                    o[4 * c + 3] = o[4 * c + 3] * corr + p * vv.w;
                }
                m = mn;
            }
        }
        __syncthreads();
    }
    float inv = 1.0f / l;
    float* dst = g_ao + (size_t)(b * NN + i) * DIM + h * DH;
#pragma unroll
    for (int d = 0; d < DH; d += 4) {
        float4 v = make_float4(o[d] * inv, o[d + 1] * inv, o[d + 2] * inv, o[d + 3] * inv);
        *(float4*)&dst[d] = v;
    }
}

// ---------------- launch -----------------------------------------------------
extern "C" void kernel_launch(void* const* d_in, const int* in_sizes, int n_in,
                              void* d_out, int out_size) {
    const float* x = (const float*)d_in[0];
    const float* norm_g = (const float*)d_in[1];
    const float* norm_b = (const float*)d_in[2];
    const float* Wq = (const float*)d_in[3];
    const float* Wkv = (const float*)d_in[4];
    const float* q_scale = (const float*)d_in[5];
    const float* k_scale = (const float*)d_in[6];
    const float* null_kv = (const float*)d_in[7];
    const float* Wout = (const float*)d_in[8];
    float* out = (float*)d_out;

    float *p_xn, *p_qraw, *p_kvraw, *p_ao;
    cudaGetSymbolAddress((void**)&p_xn, g_xn);
    cudaGetSymbolAddress((void**)&p_qraw, g_qraw);
    cudaGetSymbolAddress((void**)&p_kvraw, g_kvraw);
    cudaGetSymbolAddress((void**)&p_ao, g_ao);

    const int M = BB * NN;  // 4096

    // 1) LayerNorm (Q path)
    ln_kernel<<<M, 256>>>(x, norm_g, norm_b);

    // 2) KV projection from PRE-norm x: (4096x1024)@(1024x2048)
    sgemm_kernel<<<dim3(2 * DIM / GBN, M / GBM), 256>>>(x, Wkv, p_kvraw, M, 2 * DIM, DIM);

    // 3) Q projection from xn: (4096x1024)@(1024x1024)
    sgemm_kernel<<<dim3(DIM / GBN, M / GBM), 256>>>(p_xn, Wq, p_qraw, M, DIM, DIM);

    // 4) preps
    qprep_kernel<<<(BB * NN * HH) / 4, 128>>>(q_scale);
    kvprep_kernel<<<(BB * NN * HH) / 4, 128>>>(k_scale);
    nullprep_kernel<<<1, HH * NNUL * 32>>>(null_kv, k_scale);

    // 5) attention
    attn_kernel<<<dim3(NN / TQ, HH, BB), 64>>>();

    // 6) output projection: (4096x1024)@(1024x1024) -> d_out
    sgemm_kernel<<<dim3(DIM / GBN, M / GBM), 256>>>(p_ao, Wout, out, M, DIM, DIM);
}

// round 2
// speedup vs baseline: 1.3794x; 1.3794x over previous
#include <cuda_runtime.h>
#include <math.h>
#include <stdint.h>

#define BB 2
#define NN 2048
#define DIM 1024
#define HH 16
#define DH 64
#define NNUL 2
#define JJ (NN + NNUL)
#define SCALE 8.0f
#define LN_EPS 1e-5f

// ---------------- scratch (static device globals: allocation-guard safe) ----
__device__ float g_xn[(size_t)BB * NN * DIM];          // LayerNorm'd x (Q path)
__device__ float g_qraw[(size_t)BB * NN * DIM];        // xn @ Wq
__device__ float g_kvraw[(size_t)BB * NN * 2 * DIM];   // x @ Wkv
__device__ float g_q[(size_t)BB * HH * NN * DH];       // normalized q, (b,h,n,d)
__device__ float g_k[(size_t)BB * HH * JJ * DH];       // normalized k incl nulls, (b,h,j,d)
__device__ float g_v[(size_t)BB * HH * JJ * DH];       // v incl nulls, (b,h,j,d)
__device__ float g_ao[(size_t)BB * NN * DIM];          // attention out, (b,n,h*dh)

// ---------------- LayerNorm ------------------------------------------------
__global__ void ln_kernel(const float* __restrict__ x, const float* __restrict__ gma,
                          const float* __restrict__ bta) {
    int row = blockIdx.x;
    const float* xr = x + (size_t)row * DIM;
    float vals[4];
    float s = 0.f, ss = 0.f;
#pragma unroll
    for (int i = 0; i < 4; i++) {
        float v = xr[threadIdx.x + i * 256];
        vals[i] = v;
        s += v;
        ss += v * v;
    }
#pragma unroll
    for (int off = 16; off; off >>= 1) {
        s += __shfl_xor_sync(0xffffffffu, s, off);
        ss += __shfl_xor_sync(0xffffffffu, ss, off);
    }
    __shared__ float rs[8], rss[8];
    int w = threadIdx.x >> 5;
    if ((threadIdx.x & 31) == 0) { rs[w] = s; rss[w] = ss; }
    __syncthreads();
    if (threadIdx.x < 32) {
        float a = (threadIdx.x < 8) ? rs[threadIdx.x] : 0.f;
        float b2 = (threadIdx.x < 8) ? rss[threadIdx.x] : 0.f;
#pragma unroll
        for (int off = 4; off; off >>= 1) {
            a += __shfl_xor_sync(0xffffffffu, a, off);
            b2 += __shfl_xor_sync(0xffffffffu, b2, off);
        }
        if (threadIdx.x == 0) { rs[0] = a; rss[0] = b2; }
    }
    __syncthreads();
    float mu = rs[0] * (1.0f / DIM);
    float var = rss[0] * (1.0f / DIM) - mu * mu;
    float inv = rsqrtf(var + LN_EPS);
#pragma unroll
    for (int i = 0; i < 4; i++) {
        int d = threadIdx.x + i * 256;
        g_xn[(size_t)row * DIM + d] = (vals[i] - mu) * inv * gma[d] + bta[d];
    }
}

// ---------------- TF32 tensor-core GEMM: C = A(MxK) @ B(KxN), row-major ----
// 128x128x32 tiles, cp.async double buffer, 8 warps of 64x32 (4x4 m16n8k8).
#define TBM 128
#define TBN 128
#define TBK 32
#define AS_STRIDE 36   // [m][k] layout, bank = (4m+k)%32 -> lane permutation
#define BS_STRIDE 136  // [k][n] layout, bank = (8k+n)%32 -> lane permutation
#define AS_FLOATS (TBM * AS_STRIDE)           // 4608
#define BS_FLOATS (TBK * BS_STRIDE)           // 4352
#define STAGE_FLOATS (AS_FLOATS + BS_FLOATS)  // 8960
#define GEMM_SMEM_BYTES (2 * STAGE_FLOATS * 4)

__device__ __forceinline__ void cp_async16(void* sdst, const void* gsrc) {
    uint32_t sa = (uint32_t)__cvta_generic_to_shared(sdst);
    asm volatile("cp.async.cg.shared.global [%0], [%1], 16;\n" :: "r"(sa), "l"(gsrc));
}
__device__ __forceinline__ void cp_commit() {
    asm volatile("cp.async.commit_group;\n" ::: "memory");
}
__device__ __forceinline__ void cp_wait0() {
    asm volatile("cp.async.wait_group 0;\n" ::: "memory");
}
__device__ __forceinline__ uint32_t to_tf32(float f) {
    uint32_t u;
    asm("cvt.rna.tf32.f32 %0, %1;" : "=r"(u) : "f"(f));
    return u;
}

__global__ void __launch_bounds__(256)
tf32gemm(const float* __restrict__ A, const float* __restrict__ B,
         float* __restrict__ C, int M, int N, int K) {
    extern __shared__ float smem[];
    int tid = threadIdx.x;
    int lane = tid & 31;
    int warp = tid >> 5;
    int wm = warp >> 2;       // 0..1  -> m offset wm*64
    int wn = warp & 3;        // 0..3  -> n offset wn*32
    int row0 = blockIdx.y * TBM;
    int col0 = blockIdx.x * TBN;

    float acc[4][4][4];
#pragma unroll
    for (int i = 0; i < 4; i++)
#pragma unroll
        for (int j = 0; j < 4; j++)
#pragma unroll
            for (int r = 0; r < 4; r++) acc[i][j][r] = 0.f;

    // per-thread load coords
    int a_m = tid >> 3;            // 0..31 (+t*32)
    int a_k4 = (tid & 7) * 4;      // k offset
    int b_k = tid >> 5;            // 0..7 (+t*8)
    int b_n4 = (tid & 31) * 4;     // n offset

    int tiles = K / TBK;

    // prologue: load tile 0 into stage 0
    {
        float* As = smem;
        float* Bs = smem + AS_FLOATS;
#pragma unroll
        for (int t = 0; t < 4; t++) {
            int m = a_m + t * 32;
            cp_async16(&As[m * AS_STRIDE + a_k4], &A[(size_t)(row0 + m) * K + a_k4]);
        }
#pragma unroll
        for (int t = 0; t < 4; t++) {
            int k = b_k + t * 8;
            cp_async16(&Bs[k * BS_STRIDE + b_n4], &B[(size_t)k * N + col0 + b_n4]);
        }
        cp_commit();
    }

    for (int kt = 0; kt < tiles; kt++) {
        cp_wait0();
        __syncthreads();
        if (kt + 1 < tiles) {
            float* As = smem + ((kt + 1) & 1) * STAGE_FLOATS;
            float* Bs = As + AS_FLOATS;
            int kg = (kt + 1) * TBK;
#pragma unroll
            for (int t = 0; t < 4; t++) {
                int m = a_m + t * 32;
                cp_async16(&As[m * AS_STRIDE + a_k4], &A[(size_t)(row0 + m) * K + kg + a_k4]);
            }
#pragma unroll
            for (int t = 0; t < 4; t++) {
                int k = b_k + t * 8;
                cp_async16(&Bs[k * BS_STRIDE + b_n4], &B[(size_t)(kg + k) * N + col0 + b_n4]);
            }
            cp_commit();
        }
        const float* As = smem + (kt & 1) * STAGE_FLOATS;
        const float* Bs = As + AS_FLOATS;
        int fr = lane >> 2;        // 0..7
        int fc = lane & 3;         // 0..3
#pragma unroll
        for (int ks = 0; ks < 4; ks++) {
            int kb = ks * 8;
            uint32_t af[4][4], bf[4][2];
#pragma unroll
            for (int mt = 0; mt < 4; mt++) {
                int mb = wm * 64 + mt * 16;
                af[mt][0] = to_tf32(As[(mb + fr) * AS_STRIDE + kb + fc]);
                af[mt][1] = to_tf32(As[(mb + 8 + fr) * AS_STRIDE + kb + fc]);
                af[mt][2] = to_tf32(As[(mb + fr) * AS_STRIDE + kb + 4 + fc]);
                af[mt][3] = to_tf32(As[(mb + 8 + fr) * AS_STRIDE + kb + 4 + fc]);
            }
#pragma unroll
            for (int nt = 0; nt < 4; nt++) {
                int nb = wn * 32 + nt * 8;
                bf[nt][0] = to_tf32(Bs[(kb + fc) * BS_STRIDE + nb + fr]);
                bf[nt][1] = to_tf32(Bs[(kb + 4 + fc) * BS_STRIDE + nb + fr]);
            }
#pragma unroll
            for (int mt = 0; mt < 4; mt++)
#pragma unroll
                for (int nt = 0; nt < 4; nt++) {
                    asm volatile(
                        "mma.sync.aligned.m16n8k8.row.col.f32.tf32.tf32.f32 "
                        "{%0,%1,%2,%3}, {%4,%5,%6,%7}, {%8,%9}, {%0,%1,%2,%3};"
                        : "+f"(acc[mt][nt][0]), "+f"(acc[mt][nt][1]),
                          "+f"(acc[mt][nt][2]), "+f"(acc[mt][nt][3])
                        : "r"(af[mt][0]), "r"(af[mt][1]), "r"(af[mt][2]), "r"(af[mt][3]),
                          "r"(bf[nt][0]), "r"(bf[nt][1]));
                }
        }
        __syncthreads();
    }

    // epilogue
    int fr = lane >> 2;
    int fc = lane & 3;
#pragma unroll
    for (int mt = 0; mt < 4; mt++) {
        int row = row0 + wm * 64 + mt * 16 + fr;
#pragma unroll
        for (int nt = 0; nt < 4; nt++) {
            int col = col0 + wn * 32 + nt * 8 + fc * 2;
            *(float2*)&C[(size_t)row * N + col] = make_float2(acc[mt][nt][0], acc[mt][nt][1]);
            *(float2*)&C[(size_t)(row + 8) * N + col] = make_float2(acc[mt][nt][2], acc[mt][nt][3]);
        }
    }
}

// ---------------- q prep: l2norm * q_scale, transpose to (b,h,n,d) ----------
__global__ void qprep_kernel(const float* __restrict__ qs) {
    int gw = blockIdx.x * 4 + (threadIdx.x >> 5);
    int lane = threadIdx.x & 31;
    int h = gw % HH;
    int n = (gw / HH) % NN;
    int b = gw / (HH * NN);
    const float* src = g_qraw + (size_t)(b * NN + n) * DIM + h * DH;
    float v0 = src[lane], v1 = src[lane + 32];
    float ss = v0 * v0 + v1 * v1;
#pragma unroll
    for (int off = 16; off; off >>= 1) ss += __shfl_xor_sync(0xffffffffu, ss, off);
    float inv = 1.0f / fmaxf(sqrtf(ss), 1e-12f);
    float* dst = g_q + (size_t)((b * HH + h) * NN + n) * DH;
    dst[lane] = v0 * inv * qs[lane];
    dst[lane + 32] = v1 * inv * qs[lane + 32];
}

// ---------------- kv prep: k l2norm * k_scale, v copy; (b,h,j,d) ------------
__global__ void kvprep_kernel(const float* __restrict__ ks) {
    int gw = blockIdx.x * 4 + (threadIdx.x >> 5);
    int lane = threadIdx.x & 31;
    int h = gw % HH;
    int n = (gw / HH) % NN;
    int b = gw / (HH * NN);
    const float* row = g_kvraw + (size_t)(b * NN + n) * (2 * DIM);
    float k0 = row[h * DH + lane], k1 = row[h * DH + lane + 32];
    float v0 = row[DIM + h * DH + lane], v1 = row[DIM + h * DH + lane + 32];
    float ss = k0 * k0 + k1 * k1;
#pragma unroll
    for (int off = 16; off; off >>= 1) ss += __shfl_xor_sync(0xffffffffu, ss, off);
    float inv = 1.0f / fmaxf(sqrtf(ss), 1e-12f);
    size_t base = (size_t)((b * HH + h) * JJ + (n + NNUL)) * DH;
    g_k[base + lane] = k0 * inv * ks[lane];
    g_k[base + lane + 32] = k1 * inv * ks[lane + 32];
    g_v[base + lane] = v0;
    g_v[base + lane + 32] = v1;
}

// ---------------- null kv prep ----------------------------------------------
__global__ void nullprep_kernel(const float* __restrict__ null_kv,
                                const float* __restrict__ ks) {
    int w = threadIdx.x >> 5;   // 0..31: (h, t)
    int lane = threadIdx.x & 31;
    int h = w / NNUL;
    int t = w % NNUL;
    const float* base = null_kv + (size_t)h * (2 * NNUL) * DH;
    float k0 = base[(2 * t) * DH + lane];
    float k1 = base[(2 * t) * DH + lane + 32];
    float vv0 = base[(2 * t + 1) * DH + lane];
    float vv1 = base[(2 * t + 1) * DH + lane + 32];
    float ss = k0 * k0 + k1 * k1;
#pragma unroll
    for (int off = 16; off; off >>= 1) ss += __shfl_xor_sync(0xffffffffu, ss, off);
    float inv = 1.0f / fmaxf(sqrtf(ss), 1e-12f);
    for (int b = 0; b < BB; b++) {
        size_t o = (size_t)((b * HH + h) * JJ + t) * DH;
        g_k[o + lane] = k0 * inv * ks[lane];
        g_k[o + lane + 32] = k1 * inv * ks[lane + 32];
        g_v[o + lane] = vv0;
        g_v[o + lane + 32] = vv1;
    }
}

// ---------------- attention (flash-style, 1 thread = 1 query row) -----------
#define TQ 64
#define TK 64
__global__ void __launch_bounds__(64)
attn_kernel() {
    __shared__ float4 Ks[TK * 16];
    __shared__ float4 Vs[TK * 16];
    int b = blockIdx.z, h = blockIdx.y, qt = blockIdx.x;
    int tid = threadIdx.x;
    int i = qt * TQ + tid;                 // query row
    const float* qrow = g_q + (size_t)((b * HH + h) * NN + i) * DH;
    float q[DH];
#pragma unroll
    for (int d = 0; d < DH; d += 4) {
        float4 t = *(const float4*)&qrow[d];
        q[d] = t.x; q[d + 1] = t.y; q[d + 2] = t.z; q[d + 3] = t.w;
    }
    float m = -1e30f, l = 0.f;
    float o[DH];
#pragma unroll
    for (int d = 0; d < DH; d++) o[d] = 0.f;

    float slope = exp2f(-0.5f * (float)(h + 1));
    int mycol = i + NNUL;                  // my max visible column
    int nkeys = qt * TQ + TQ - 1 + NNUL + 1;

    const float4* kbase = (const float4*)(g_k + (size_t)(b * HH + h) * JJ * DH);
    const float4* vbase = (const float4*)(g_v + (size_t)(b * HH + h) * JJ * DH);

    for (int j0 = 0; j0 < nkeys; j0 += TK) {
        int cnt = min(TK, nkeys - j0);
        for (int t = tid; t < cnt * 16; t += 64) {
            Ks[t] = kbase[(size_t)j0 * 16 + t];
            Vs[t] = vbase[(size_t)j0 * 16 + t];
        }
        __syncthreads();
        for (int jj = 0; jj < cnt; jj++) {
            int col = j0 + jj;
            if (col <= mycol) {
                float s = 0.f;
#pragma unroll
                for (int c = 0; c < 16; c++) {
                    float4 kk = Ks[jj * 16 + c];
                    s = fmaf(q[4 * c + 0], kk.x, s);
                    s = fmaf(q[4 * c + 1], kk.y, s);
                    s = fmaf(q[4 * c + 2], kk.z, s);
                    s = fmaf(q[4 * c + 3], kk.w, s);
                }
                s = s * SCALE + slope * (float)(col - mycol);
                float mn = fmaxf(m, s);
                float corr = __expf(m - mn);
                float p = __expf(s - mn);
                l = l * corr + p;
#pragma unroll
                for (int c = 0; c < 16; c++) {
                    float4 vv = Vs[jj * 16 + c];
                    o[4 * c + 0] = o[4 * c + 0] * corr + p * vv.x;
                    o[4 * c + 1] = o[4 * c + 1] * corr + p * vv.y;
                    o[4 * c + 2] = o[4 * c + 2] * corr + p * vv.z;
                    o[4 * c + 3] = o[4 * c + 3] * corr + p * vv.w;
                }
                m = mn;
            }
        }
        __syncthreads();
    }
    float inv = 1.0f / l;
    float* dst = g_ao + (size_t)(b * NN + i) * DIM + h * DH;
#pragma unroll
    for (int d = 0; d < DH; d += 4) {
        float4 v = make_float4(o[d] * inv, o[d + 1] * inv, o[d + 2] * inv, o[d + 3] * inv);
        *(float4*)&dst[d] = v;
    }
}

// ---------------- launch -----------------------------------------------------
extern "C" void kernel_launch(void* const* d_in, const int* in_sizes, int n_in,
                              void* d_out, int out_size) {
    const float* x = (const float*)d_in[0];
    const float* norm_g = (const float*)d_in[1];
    const float* norm_b = (const float*)d_in[2];
    const float* Wq = (const float*)d_in[3];
    const float* Wkv = (const float*)d_in[4];
    const float* q_scale = (const float*)d_in[5];
    const float* k_scale = (const float*)d_in[6];
    const float* null_kv = (const float*)d_in[7];
    const float* Wout = (const float*)d_in[8];
    float* out = (float*)d_out;

    float *p_xn, *p_qraw, *p_kvraw, *p_ao;
    cudaGetSymbolAddress((void**)&p_xn, g_xn);
    cudaGetSymbolAddress((void**)&p_qraw, g_qraw);
    cudaGetSymbolAddress((void**)&p_kvraw, g_kvraw);
    cudaGetSymbolAddress((void**)&p_ao, g_ao);

    static int smem_set = 0;
    if (!smem_set) {
        cudaFuncSetAttribute(tf32gemm, cudaFuncAttributeMaxDynamicSharedMemorySize,
                             GEMM_SMEM_BYTES);
        smem_set = 1;
    }

    const int M = BB * NN;  // 4096

    // 1) LayerNorm (Q path)
    ln_kernel<<<M, 256>>>(x, norm_g, norm_b);

    // 2) KV projection from PRE-norm x
    tf32gemm<<<dim3(2 * DIM / TBN, M / TBM), 256, GEMM_SMEM_BYTES>>>(
        x, Wkv, p_kvraw, M, 2 * DIM, DIM);

    // 3) Q projection from xn
    tf32gemm<<<dim3(DIM / TBN, M / TBM), 256, GEMM_SMEM_BYTES>>>(
        p_xn, Wq, p_qraw, M, DIM, DIM);

    // 4) preps
    qprep_kernel<<<(BB * NN * HH) / 4, 128>>>(q_scale);
    kvprep_kernel<<<(BB * NN * HH) / 4, 128>>>(k_scale);
    nullprep_kernel<<<1, HH * NNUL * 32>>>(null_kv, k_scale);

    // 5) attention
    attn_kernel<<<dim3(NN / TQ, HH, BB), 64>>>();

    // 6) output projection
    tf32gemm<<<dim3(DIM / TBN, M / TBM), 256, GEMM_SMEM_BYTES>>>(
        p_ao, Wout, out, M, DIM, DIM);
}

// round 4
// speedup vs baseline: 2.8026x; 2.0317x over previous
#include <cuda_runtime.h>
#include <cuda_bf16.h>
#include <math.h>
#include <stdint.h>

#define BB 2
#define NN 2048
#define DIM 1024
#define HH 16
#define DH 64
#define NNUL 2
#define JJ (NN + NNUL)
#define SCALE 8.0f
#define LN_EPS 1e-5f

// ---------------- scratch ----------------------------------------------------
__device__ float g_xn[(size_t)BB * NN * DIM];
__device__ float g_qraw[(size_t)BB * NN * DIM];
__device__ float g_kvraw[(size_t)BB * NN * 2 * DIM];
__device__ float g_q[(size_t)BB * HH * NN * DH];
__device__ float g_k[(size_t)BB * HH * JJ * DH];
__device__ float g_v[(size_t)BB * HH * JJ * DH];
__device__ float g_ao[(size_t)BB * NN * DIM];

// ---------------- LayerNorm ------------------------------------------------
__global__ void ln_kernel(const float* __restrict__ x, const float* __restrict__ gma,
                          const float* __restrict__ bta) {
    int row = blockIdx.x;
    const float* xr = x + (size_t)row * DIM;
    float vals[4];
    float s = 0.f, ss = 0.f;
#pragma unroll
    for (int i = 0; i < 4; i++) {
        float v = xr[threadIdx.x + i * 256];
        vals[i] = v;
        s += v;
        ss += v * v;
    }
#pragma unroll
    for (int off = 16; off; off >>= 1) {
        s += __shfl_xor_sync(0xffffffffu, s, off);
        ss += __shfl_xor_sync(0xffffffffu, ss, off);
    }
    __shared__ float rs[8], rss[8];
    int w = threadIdx.x >> 5;
    if ((threadIdx.x & 31) == 0) { rs[w] = s; rss[w] = ss; }
    __syncthreads();
    if (threadIdx.x < 32) {
        float a = (threadIdx.x < 8) ? rs[threadIdx.x] : 0.f;
        float b2 = (threadIdx.x < 8) ? rss[threadIdx.x] : 0.f;
#pragma unroll
        for (int off = 4; off; off >>= 1) {
            a += __shfl_xor_sync(0xffffffffu, a, off);
            b2 += __shfl_xor_sync(0xffffffffu, b2, off);
        }
        if (threadIdx.x == 0) { rs[0] = a; rss[0] = b2; }
    }
    __syncthreads();
    float mu = rs[0] * (1.0f / DIM);
    float var = rss[0] * (1.0f / DIM) - mu * mu;
    float inv = rsqrtf(var + LN_EPS);
#pragma unroll
    for (int i = 0; i < 4; i++) {
        int d = threadIdx.x + i * 256;
        g_xn[(size_t)row * DIM + d] = (vals[i] - mu) * inv * gma[d] + bta[d];
    }
}

// ---------------- TF32 tensor-core GEMM -------------------------------------
#define TBM 128
#define TBN 128
#define TBK 32
#define AS_STRIDE 36
#define BS_STRIDE 136
#define AS_FLOATS (TBM * AS_STRIDE)
#define BS_FLOATS (TBK * BS_STRIDE)
#define STAGE_FLOATS (AS_FLOATS + BS_FLOATS)
#define GEMM_SMEM_BYTES (2 * STAGE_FLOATS * 4)

__device__ __forceinline__ void cp_async16(void* sdst, const void* gsrc) {
    uint32_t sa = (uint32_t)__cvta_generic_to_shared(sdst);
    asm volatile("cp.async.cg.shared.global [%0], [%1], 16;\n" :: "r"(sa), "l"(gsrc));
}
__device__ __forceinline__ void cp_commit() {
    asm volatile("cp.async.commit_group;\n" ::: "memory");
}
__device__ __forceinline__ void cp_wait0() {
    asm volatile("cp.async.wait_group 0;\n" ::: "memory");
}
__device__ __forceinline__ uint32_t to_tf32(float f) {
    uint32_t u;
    asm("cvt.rna.tf32.f32 %0, %1;" : "=r"(u) : "f"(f));
    return u;
}

__global__ void __launch_bounds__(256)
tf32gemm(const float* __restrict__ A, const float* __restrict__ B,
         float* __restrict__ C, int M, int N, int K) {
    extern __shared__ float smem[];
    int tid = threadIdx.x;
    int lane = tid & 31;
    int warp = tid >> 5;
    int wm = warp >> 2;
    int wn = warp & 3;
    int row0 = blockIdx.y * TBM;
    int col0 = blockIdx.x * TBN;

    float acc[4][4][4];
#pragma unroll
    for (int i = 0; i < 4; i++)
#pragma unroll
        for (int j = 0; j < 4; j++)
#pragma unroll
            for (int r = 0; r < 4; r++) acc[i][j][r] = 0.f;

    int a_m = tid >> 3;
    int a_k4 = (tid & 7) * 4;
    int b_k = tid >> 5;
    int b_n4 = (tid & 31) * 4;
    int tiles = K / TBK;

    {
        float* As = smem;
        float* Bs = smem + AS_FLOATS;
#pragma unroll
        for (int t = 0; t < 4; t++) {
            int m = a_m + t * 32;
            cp_async16(&As[m * AS_STRIDE + a_k4], &A[(size_t)(row0 + m) * K + a_k4]);
        }
#pragma unroll
        for (int t = 0; t < 4; t++) {
            int k = b_k + t * 8;
            cp_async16(&Bs[k * BS_STRIDE + b_n4], &B[(size_t)k * N + col0 + b_n4]);
        }
        cp_commit();
    }

    for (int kt = 0; kt < tiles; kt++) {
        cp_wait0();
        __syncthreads();
        if (kt + 1 < tiles) {
            float* As = smem + ((kt + 1) & 1) * STAGE_FLOATS;
            float* Bs = As + AS_FLOATS;
            int kg = (kt + 1) * TBK;
#pragma unroll
            for (int t = 0; t < 4; t++) {
                int m = a_m + t * 32;
                cp_async16(&As[m * AS_STRIDE + a_k4], &A[(size_t)(row0 + m) * K + kg + a_k4]);
            }
#pragma unroll
            for (int t = 0; t < 4; t++) {
                int k = b_k + t * 8;
                cp_async16(&Bs[k * BS_STRIDE + b_n4], &B[(size_t)(kg + k) * N + col0 + b_n4]);
            }
            cp_commit();
        }
        const float* As = smem + (kt & 1) * STAGE_FLOATS;
        const float* Bs = As + AS_FLOATS;
        int fr = lane >> 2;
        int fc = lane & 3;
#pragma unroll
        for (int ks = 0; ks < 4; ks++) {
            int kb = ks * 8;
            uint32_t af[4][4], bf[4][2];
#pragma unroll
            for (int mt = 0; mt < 4; mt++) {
                int mb = wm * 64 + mt * 16;
                af[mt][0] = to_tf32(As[(mb + fr) * AS_STRIDE + kb + fc]);
                af[mt][1] = to_tf32(As[(mb + 8 + fr) * AS_STRIDE + kb + fc]);
                af[mt][2] = to_tf32(As[(mb + fr) * AS_STRIDE + kb + 4 + fc]);
                af[mt][3] = to_tf32(As[(mb + 8 + fr) * AS_STRIDE + kb + 4 + fc]);
            }
#pragma unroll
            for (int nt = 0; nt < 4; nt++) {
                int nb = wn * 32 + nt * 8;
                bf[nt][0] = to_tf32(Bs[(kb + fc) * BS_STRIDE + nb + fr]);
                bf[nt][1] = to_tf32(Bs[(kb + 4 + fc) * BS_STRIDE + nb + fr]);
            }
#pragma unroll
            for (int mt = 0; mt < 4; mt++)
#pragma unroll
                for (int nt = 0; nt < 4; nt++) {
                    asm volatile(
                        "mma.sync.aligned.m16n8k8.row.col.f32.tf32.tf32.f32 "
                        "{%0,%1,%2,%3}, {%4,%5,%6,%7}, {%8,%9}, {%0,%1,%2,%3};"
                        : "+f"(acc[mt][nt][0]), "+f"(acc[mt][nt][1]),
                          "+f"(acc[mt][nt][2]), "+f"(acc[mt][nt][3])
                        : "r"(af[mt][0]), "r"(af[mt][1]), "r"(af[mt][2]), "r"(af[mt][3]),
                          "r"(bf[nt][0]), "r"(bf[nt][1]));
                }
        }
        __syncthreads();
    }

    int fr = lane >> 2;
    int fc = lane & 3;
#pragma unroll
    for (int mt = 0; mt < 4; mt++) {
        int row = row0 + wm * 64 + mt * 16 + fr;
#pragma unroll
        for (int nt = 0; nt < 4; nt++) {
            int col = col0 + wn * 32 + nt * 8 + fc * 2;
            *(float2*)&C[(size_t)row * N + col] = make_float2(acc[mt][nt][0], acc[mt][nt][1]);
            *(float2*)&C[(size_t)(row + 8) * N + col] = make_float2(acc[mt][nt][2], acc[mt][nt][3]);
        }
    }
}

// ---------------- preps ------------------------------------------------------
__global__ void qprep_kernel(const float* __restrict__ qs) {
    int gw = blockIdx.x * 4 + (threadIdx.x >> 5);
    int lane = threadIdx.x & 31;
    int h = gw % HH;
    int n = (gw / HH) % NN;
    int b = gw / (HH * NN);
    const float* src = g_qraw + (size_t)(b * NN + n) * DIM + h * DH;
    float v0 = src[lane], v1 = src[lane + 32];
    float ss = v0 * v0 + v1 * v1;
#pragma unroll
    for (int off = 16; off; off >>= 1) ss += __shfl_xor_sync(0xffffffffu, ss, off);
    float inv = 1.0f / fmaxf(sqrtf(ss), 1e-12f);
    float* dst = g_q + (size_t)((b * HH + h) * NN + n) * DH;
    dst[lane] = v0 * inv * qs[lane];
    dst[lane + 32] = v1 * inv * qs[lane + 32];
}

__global__ void kvprep_kernel(const float* __restrict__ ks) {
    int gw = blockIdx.x * 4 + (threadIdx.x >> 5);
    int lane = threadIdx.x & 31;
    int h = gw % HH;
    int n = (gw / HH) % NN;
    int b = gw / (HH * NN);
    const float* row = g_kvraw + (size_t)(b * NN + n) * (2 * DIM);
    float k0 = row[h * DH + lane], k1 = row[h * DH + lane + 32];
    float v0 = row[DIM + h * DH + lane], v1 = row[DIM + h * DH + lane + 32];
    float ss = k0 * k0 + k1 * k1;
#pragma unroll
    for (int off = 16; off; off >>= 1) ss += __shfl_xor_sync(0xffffffffu, ss, off);
    float inv = 1.0f / fmaxf(sqrtf(ss), 1e-12f);
    size_t base = (size_t)((b * HH + h) * JJ + (n + NNUL)) * DH;
    g_k[base + lane] = k0 * inv * ks[lane];
    g_k[base + lane + 32] = k1 * inv * ks[lane + 32];
    g_v[base + lane] = v0;
    g_v[base + lane + 32] = v1;
}

__global__ void nullprep_kernel(const float* __restrict__ null_kv,
                                const float* __restrict__ ks) {
    int w = threadIdx.x >> 5;
    int lane = threadIdx.x & 31;
    int h = w / NNUL;
    int t = w % NNUL;
    const float* base = null_kv + (size_t)h * (2 * NNUL) * DH;
    float k0 = base[(2 * t) * DH + lane];
    float k1 = base[(2 * t) * DH + lane + 32];
    float vv0 = base[(2 * t + 1) * DH + lane];
    float vv1 = base[(2 * t + 1) * DH + lane + 32];
    float ss = k0 * k0 + k1 * k1;
#pragma unroll
    for (int off = 16; off; off >>= 1) ss += __shfl_xor_sync(0xffffffffu, ss, off);
    float inv = 1.0f / fmaxf(sqrtf(ss), 1e-12f);
    for (int b = 0; b < BB; b++) {
        size_t o = (size_t)((b * HH + h) * JJ + t) * DH;
        g_k[o + lane] = k0 * inv * ks[lane];
        g_k[o + lane + 32] = k1 * inv * ks[lane + 32];
        g_v[o + lane] = vv0;
        g_v[o + lane + 32] = vv1;
    }
}

// ---------------- mma attention ---------------------------------------------
// 64 q-rows x 64-key tiles, 4 warps x 16 rows, bf16 m16n8k16 with 3-term split.
#define KSTR 72   // halves; conflict-free fragment loads
#define QSTR 68   // floats; multiple of 4 -> float4-aligned staging
#define ATTN_SMEM (4 * 64 * KSTR * 2)

#define MMA_BF16(C, A, B0, B1)                                              \
    asm volatile(                                                           \
        "mma.sync.aligned.m16n8k16.row.col.f32.bf16.bf16.f32 "              \
        "{%0,%1,%2,%3}, {%4,%5,%6,%7}, {%8,%9}, {%0,%1,%2,%3};"             \
        : "+f"(C[0]), "+f"(C[1]), "+f"(C[2]), "+f"(C[3])                    \
        : "r"(A[0]), "r"(A[1]), "r"(A[2]), "r"(A[3]), "r"(B0), "r"(B1))

__device__ __forceinline__ uint32_t pack_bf2(float a, float b) {
    __nv_bfloat162 t;
    t.x = __float2bfloat16_rn(a);
    t.y = __float2bfloat16_rn(b);
    return *(uint32_t*)&t;
}

__global__ void __launch_bounds__(128)
attn_mma_kernel() {
    extern __shared__ char sm[];
    __nv_bfloat16* Kh = (__nv_bfloat16*)sm;                        // [64][KSTR]
    __nv_bfloat16* Kl = Kh + 64 * KSTR;
    __nv_bfloat16* Vh = Kl + 64 * KSTR;                            // transposed [dh][key]
    __nv_bfloat16* Vl = Vh + 64 * KSTR;
    float* Qs = (float*)sm;                                        // overlay, used once

    int b = blockIdx.z, h = blockIdx.y;
    int qt = (gridDim.x - 1) - blockIdx.x;       // big tiles first
    int tid = threadIdx.x;
    int w = tid >> 5;
    int lane = tid & 31;
    int fr = lane >> 2;
    int fc = lane & 3;

    size_t qbase = (size_t)((b * HH + h) * NN + qt * 64) * DH;
    size_t kvbase = (size_t)(b * HH + h) * JJ * DH;

    // ---- stage Q tile (fp32) then extract per-warp A fragments (hi/lo bf16)
    for (int i = tid; i < 64 * 16; i += 128) {
        int r = i >> 4, c4 = (i & 15) * 4;
        *(float4*)&Qs[r * QSTR + c4] = *(const float4*)&g_q[qbase + (size_t)r * DH + c4];
    }
    __syncthreads();

    uint32_t qh[4][4], ql[4][4];
#pragma unroll
    for (int kc = 0; kc < 4; kc++) {
        int lr = w * 16 + fr;
        int c = kc * 16 + 2 * fc;
#pragma unroll
        for (int p = 0; p < 4; p++) {
            int rr = lr + (p & 1) * 8;
            int cc = c + (p >> 1) * 8;
            float x0 = Qs[rr * QSTR + cc], x1 = Qs[rr * QSTR + cc + 1];
            float h0 = __bfloat162float(__float2bfloat16_rn(x0));
            float h1 = __bfloat162float(__float2bfloat16_rn(x1));
            qh[kc][p] = pack_bf2(h0, h1);
            ql[kc][p] = pack_bf2(x0 - h0, x1 - h1);
        }
    }

    float O[8][4];
#pragma unroll
    for (int nb = 0; nb < 8; nb++)
#pragma unroll
        for (int r = 0; r < 4; r++) O[nb][r] = 0.f;

    float slope = exp2f(-0.5f * (float)(h + 1));
    int row0g = qt * 64 + w * 16 + fr;
    int row1g = row0g + 8;
    int my0 = row0g + NNUL, my1 = row1g + NNUL;
    float m0 = -1e30f, m1 = -1e30f, l0 = 0.f, l1 = 0.f;

    int nkeys = min(qt * 64 + 64 + NNUL, JJ);

    for (int j0 = 0; j0 < nkeys; j0 += 64) {
        __syncthreads();   // protect smem before overwrite (incl. Qs overlay)
        // ---- stage K (row-major) and V (transposed), bf16 hi/lo, zero-fill OOB
        for (int i = tid; i < 64 * 16; i += 128) {
            int r = i >> 4, c4 = (i & 15) * 4;
            int j = j0 + r;
            float4 kk = make_float4(0.f, 0.f, 0.f, 0.f);
            float4 vv = make_float4(0.f, 0.f, 0.f, 0.f);
            if (j < JJ) {
                kk = *(const float4*)&g_k[kvbase + (size_t)j * DH + c4];
                vv = *(const float4*)&g_v[kvbase + (size_t)j * DH + c4];
            }
            float ke[4] = {kk.x, kk.y, kk.z, kk.w};
            float ve[4] = {vv.x, vv.y, vv.z, vv.w};
#pragma unroll
            for (int e = 0; e < 4; e++) {
                __nv_bfloat16 khb = __float2bfloat16_rn(ke[e]);
                Kh[r * KSTR + c4 + e] = khb;
                Kl[r * KSTR + c4 + e] = __float2bfloat16_rn(ke[e] - __bfloat162float(khb));
                __nv_bfloat16 vhb = __float2bfloat16_rn(ve[e]);
                Vh[(c4 + e) * KSTR + r] = vhb;
                Vl[(c4 + e) * KSTR + r] = __float2bfloat16_rn(ve[e] - __bfloat162float(vhb));
            }
        }
        __syncthreads();

        // ---- S = Q . K^T (3-term split)
        float S[8][4];
#pragma unroll
        for (int nb = 0; nb < 8; nb++)
#pragma unroll
            for (int r = 0; r < 4; r++) S[nb][r] = 0.f;

#pragma unroll
        for (int kc = 0; kc < 4; kc++) {
#pragma unroll
            for (int nb = 0; nb < 8; nb++) {
                int krow = nb * 8 + fr;
                int kcol = kc * 16 + 2 * fc;
                uint32_t b0h = *(uint32_t*)&Kh[krow * KSTR + kcol];
                uint32_t b1h = *(uint32_t*)&Kh[krow * KSTR + kcol + 8];
                uint32_t b0l = *(uint32_t*)&Kl[krow * KSTR + kcol];
                uint32_t b1l = *(uint32_t*)&Kl[krow * KSTR + kcol + 8];
                MMA_BF16(S[nb], qh[kc], b0h, b1h);
                MMA_BF16(S[nb], qh[kc], b0l, b1l);
                MMA_BF16(S[nb], ql[kc], b0h, b1h);
            }
        }

        // ---- bias + mask + tile max
        float mt0 = -1e30f, mt1 = -1e30f;
#pragma unroll
        for (int nb = 0; nb < 8; nb++) {
#pragma unroll
            for (int e = 0; e < 2; e++) {
                int col = j0 + nb * 8 + 2 * fc + e;
                float s0 = S[nb][e] * SCALE + slope * (float)(col - my0);
                if (col > my0) s0 = -1e30f;
                S[nb][e] = s0;
                mt0 = fmaxf(mt0, s0);
                float s1 = S[nb][2 + e] * SCALE + slope * (float)(col - my1);
                if (col > my1) s1 = -1e30f;
                S[nb][2 + e] = s1;
                mt1 = fmaxf(mt1, s1);
            }
        }
#pragma unroll
        for (int off = 1; off <= 2; off <<= 1) {
            mt0 = fmaxf(mt0, __shfl_xor_sync(0xffffffffu, mt0, off));
            mt1 = fmaxf(mt1, __shfl_xor_sync(0xffffffffu, mt1, off));
        }
        float mn0 = fmaxf(m0, mt0), mn1 = fmaxf(m1, mt1);
        float c0 = __expf(m0 - mn0), c1 = __expf(m1 - mn1);
        m0 = mn0; m1 = mn1;

        float ps0 = 0.f, ps1 = 0.f;
#pragma unroll
        for (int nb = 0; nb < 8; nb++) {
#pragma unroll
            for (int e = 0; e < 2; e++) {
                float p0 = __expf(S[nb][e] - m0);
                float p1 = __expf(S[nb][2 + e] - m1);
                S[nb][e] = p0; S[nb][2 + e] = p1;
                ps0 += p0; ps1 += p1;
            }
        }
        l0 = l0 * c0 + ps0;
        l1 = l1 * c1 + ps1;
#pragma unroll
        for (int nb = 0; nb < 8; nb++) {
            O[nb][0] *= c0; O[nb][1] *= c0;
            O[nb][2] *= c1; O[nb][3] *= c1;
        }

        // ---- P fragments (hi/lo)
        uint32_t ph[4][4], pl[4][4];
#pragma unroll
        for (int kc = 0; kc < 4; kc++) {
#pragma unroll
            for (int p = 0; p < 4; p++) {
                float x0 = S[2 * kc + (p >> 1)][(p & 1) * 2 + 0];
                float x1 = S[2 * kc + (p >> 1)][(p & 1) * 2 + 1];
                float h0 = __bfloat162float(__float2bfloat16_rn(x0));
                float h1 = __bfloat162float(__float2bfloat16_rn(x1));
                ph[kc][p] = pack_bf2(h0, h1);
                pl[kc][p] = pack_bf2(x0 - h0, x1 - h1);
            }
        }

        // ---- O += P . V  (3-term split)  V transposed: Vh[dh][key]
#pragma unroll
        for (int kc = 0; kc < 4; kc++) {
#pragma unroll
            for (int nb = 0; nb < 8; nb++) {
                int drow = nb * 8 + fr;
                int kcol = kc * 16 + 2 * fc;
                uint32_t b0h = *(uint32_t*)&Vh[drow * KSTR + kcol];
                uint32_t b1h = *(uint32_t*)&Vh[drow * KSTR + kcol + 8];
                uint32_t b0l = *(uint32_t*)&Vl[drow * KSTR + kcol];
                uint32_t b1l = *(uint32_t*)&Vl[drow * KSTR + kcol + 8];
                MMA_BF16(O[nb], ph[kc], b0h, b1h);
                MMA_BF16(O[nb], ph[kc], b0l, b1l);
                MMA_BF16(O[nb], pl[kc], b0h, b1h);
            }
        }
    }

    // ---- epilogue: row-sum reduce, normalize, store
#pragma unroll
    for (int off = 1; off <= 2; off <<= 1) {
        l0 += __shfl_xor_sync(0xffffffffu, l0, off);
        l1 += __shfl_xor_sync(0xffffffffu, l1, off);
    }
    float i0 = 1.0f / l0, i1 = 1.0f / l1;
#pragma unroll
    for (int nb = 0; nb < 8; nb++) {
        int col = h * DH + nb * 8 + 2 * fc;
        *(float2*)&g_ao[(size_t)(b * NN + row0g) * DIM + col] =
            make_float2(O[nb][0] * i0, O[nb][1] * i0);
        *(float2*)&g_ao[(size_t)(b * NN + row1g) * DIM + col] =
            make_float2(O[nb][2] * i1, O[nb][3] * i1);
    }
}

// ---------------- launch -----------------------------------------------------
extern "C" void kernel_launch(void* const* d_in, const int* in_sizes, int n_in,
                              void* d_out, int out_size) {
    const float* x = (const float*)d_in[0];
    const float* norm_g = (const float*)d_in[1];
    const float* norm_b = (const float*)d_in[2];
    const float* Wq = (const float*)d_in[3];
    const float* Wkv = (const float*)d_in[4];
    const float* q_scale = (const float*)d_in[5];
    const float* k_scale = (const float*)d_in[6];
    const float* null_kv = (const float*)d_in[7];
    const float* Wout = (const float*)d_in[8];
    float* out = (float*)d_out;

    float *p_xn, *p_qraw, *p_kvraw, *p_ao;
    cudaGetSymbolAddress((void**)&p_xn, g_xn);
    cudaGetSymbolAddress((void**)&p_qraw, g_qraw);
    cudaGetSymbolAddress((void**)&p_kvraw, g_kvraw);
    cudaGetSymbolAddress((void**)&p_ao, g_ao);

    static int smem_set = 0;
    if (!smem_set) {
        cudaFuncSetAttribute(tf32gemm, cudaFuncAttributeMaxDynamicSharedMemorySize,
                             GEMM_SMEM_BYTES);
        smem_set = 1;
    }

    const int M = BB * NN;

    ln_kernel<<<M, 256>>>(x, norm_g, norm_b);
    tf32gemm<<<dim3(2 * DIM / TBN, M / TBM), 256, GEMM_SMEM_BYTES>>>(
        x, Wkv, p_kvraw, M, 2 * DIM, DIM);
    tf32gemm<<<dim3(DIM / TBN, M / TBM), 256, GEMM_SMEM_BYTES>>>(
        p_xn, Wq, p_qraw, M, DIM, DIM);

    qprep_kernel<<<(BB * NN * HH) / 4, 128>>>(q_scale);
    kvprep_kernel<<<(BB * NN * HH) / 4, 128>>>(k_scale);
    nullprep_kernel<<<1, HH * NNUL * 32>>>(null_kv, k_scale);

    attn_mma_kernel<<<dim3(NN / 64, HH, BB), 128, ATTN_SMEM>>>();

    tf32gemm<<<dim3(DIM / TBN, M / TBM), 256, GEMM_SMEM_BYTES>>>(
        p_ao, Wout, out, M, DIM, DIM);
}